// round 4
// baseline (speedup 1.0000x reference)
#include <cuda_runtime.h>
#include <mma.h>
#include <math.h>

using namespace nvcuda;

// Problem constants
#define NTOK 2048   // B*L
#define DD   256
#define HH   8
#define DKK  32
#define NLAY 4
#define VV   2048
#define FFD  1024
#define LL   256
#define BB   8
#define EPSF 1e-5f

// ---------------- scratch (no allocation allowed) ----------------
__device__ float g_x [NTOK*DD];
__device__ float g_xn[NTOK*DD];
__device__ float g_q [NTOK*DD];
__device__ float g_k [NTOK*DD];
__device__ float g_v [NTOK*DD];
__device__ float g_z [NTOK*DD];
__device__ float g_ff[NTOK*FFD];

// ---------------- embedding ----------------
__global__ void embed_k(const int* __restrict__ tok, const int* __restrict__ pos,
                        const float* __restrict__ vt, const float* __restrict__ ct,
                        const float* __restrict__ pt) {
    int n = blockIdx.x, d = threadIdx.x;
    int t = tok[n], p = pos[n];
    g_x[n*DD + d] = vt[t*DD + d] * 16.0f          // sqrt(256)
                  + ct[(p % 3)*DD + d]
                  + pt[(p / 3)*DD + d];
}

// ---------------- layernorm (one block per row, D=256) ----------------
__global__ void ln_k(const float* __restrict__ in, float* __restrict__ out,
                     const float* __restrict__ g, const float* __restrict__ b) {
    int n = blockIdx.x, d = threadIdx.x;
    float v = in[n*DD + d];
    __shared__ float sh[16];
    float s = v, s2 = v*v;
    #pragma unroll
    for (int o = 16; o > 0; o >>= 1) {
        s  += __shfl_xor_sync(0xffffffffu, s,  o);
        s2 += __shfl_xor_sync(0xffffffffu, s2, o);
    }
    int wid = d >> 5, lid = d & 31;
    if (lid == 0) { sh[wid] = s; sh[wid + 8] = s2; }
    __syncthreads();
    float ts = 0.f, ts2 = 0.f;
    #pragma unroll
    for (int i = 0; i < 8; i++) { ts += sh[i]; ts2 += sh[i + 8]; }
    float mean = ts * (1.0f/DD);
    float var  = ts2 * (1.0f/DD) - mean*mean;
    out[n*DD + d] = (v - mean) * rsqrtf(var + EPSF) * g[d] + b[d];
}

// ---------------- WMMA tf32 GEMM body: C = A(MxK) @ B(KxN) --------------------
// 64x64 block tile, BK=16, 128 threads = 4 warps in 2x2 grid, each warp 32x32
// (2x2 m16n16k8 tf32 fragments, fp32 accumulate).
// EPI: 0=none, 1=bias, 2=bias+relu, 3=residual, 4=bias+residual
__device__ __forceinline__ void gemm_body(
        const float* __restrict__ A, const float* __restrict__ B,
        const float* __restrict__ bias, const float* __restrict__ Cin,
        float* __restrict__ C, int Nn, int K,
        int row0, int col0,
        float (*As)[16], float (*Bs)[64], float (*Cs)[64], int EPI) {
    int tid = threadIdx.x;
    int w  = tid >> 5;
    int wr = w >> 1, wc = w & 1;              // 2x2 warp grid
    int am = tid >> 2,  aq = (tid & 3)  * 4;  // A: rows am, am+32; 4 k-elems
    int bk = tid >> 4,  bq = (tid & 15) * 4;  // B: k-rows bk, bk+8; 4 n-elems

    wmma::fragment<wmma::matrix_a, 16, 16, 8, wmma::precision::tf32, wmma::row_major> af;
    wmma::fragment<wmma::matrix_b, 16, 16, 8, wmma::precision::tf32, wmma::row_major> bf;
    wmma::fragment<wmma::accumulator, 16, 16, 8, float> cf[2][2];
    #pragma unroll
    for (int i = 0; i < 2; i++)
        #pragma unroll
        for (int j = 0; j < 2; j++) wmma::fill_fragment(cf[i][j], 0.0f);

    const float* Ap0 = A + (size_t)(row0 + am)*K + aq;
    const float* Ap1 = Ap0 + (size_t)32*K;
    const float* Bp0 = B + (size_t)bk*Nn + col0 + bq;
    const float* Bp1 = Bp0 + (size_t)8*Nn;

    float4 a0 = *(const float4*)(Ap0);
    float4 a1 = *(const float4*)(Ap1);
    float4 b0 = *(const float4*)(Bp0);
    float4 b1 = *(const float4*)(Bp1);

    for (int k0 = 0; k0 < K; k0 += 16) {
        *(float4*)(&As[am     ][aq]) = a0;
        *(float4*)(&As[am + 32][aq]) = a1;
        *(float4*)(&Bs[bk     ][bq]) = b0;
        *(float4*)(&Bs[bk +  8][bq]) = b1;
        __syncthreads();

        if (k0 + 16 < K) {                    // prefetch next k-tile into regs
            a0 = *(const float4*)(Ap0 + k0 + 16);
            a1 = *(const float4*)(Ap1 + k0 + 16);
            b0 = *(const float4*)(Bp0 + (size_t)(k0 + 16)*Nn);
            b1 = *(const float4*)(Bp1 + (size_t)(k0 + 16)*Nn);
        }

        #pragma unroll
        for (int kc = 0; kc < 16; kc += 8) {
            #pragma unroll
            for (int mi = 0; mi < 2; mi++) {
                wmma::load_matrix_sync(af, &As[wr*32 + mi*16][kc], 16);
                #pragma unroll
                for (int t = 0; t < af.num_elements; t++)
                    af.x[t] = wmma::__float_to_tf32(af.x[t]);
                #pragma unroll
                for (int ni = 0; ni < 2; ni++) {
                    wmma::load_matrix_sync(bf, &Bs[kc][wc*32 + ni*16], 64);
                    #pragma unroll
                    for (int t = 0; t < bf.num_elements; t++)
                        bf.x[t] = wmma::__float_to_tf32(bf.x[t]);
                    wmma::mma_sync(cf[mi][ni], af, bf, cf[mi][ni]);
                }
            }
        }
        __syncthreads();
    }

    // store fragments to smem, then elementwise epilogue
    #pragma unroll
    for (int mi = 0; mi < 2; mi++)
        #pragma unroll
        for (int ni = 0; ni < 2; ni++)
            wmma::store_matrix_sync(&Cs[wr*32 + mi*16][wc*32 + ni*16],
                                    cf[mi][ni], 64, wmma::mem_row_major);
    __syncthreads();

    for (int idx = tid; idx < 64*64; idx += 128) {
        int r = idx >> 6, c = idx & 63;
        float val = Cs[r][c];
        int gr = row0 + r, gc = col0 + c;
        if (EPI == 1 || EPI == 2 || EPI == 4) val += bias[gc];
        if (EPI == 2)                         val = fmaxf(val, 0.f);
        if (EPI == 3 || EPI == 4)             val += Cin[(size_t)gr*Nn + gc];
        C[(size_t)gr*Nn + gc] = val;
    }
}

__global__ void __launch_bounds__(128)
gemm_k(const float* __restrict__ A, const float* __restrict__ B,
       const float* __restrict__ bias, const float* __restrict__ Cin,
       float* __restrict__ C, int Nn, int K, int EPI) {
    __shared__ float As[64][16];
    __shared__ float Bs[16][64];
    __shared__ float Cs[64][64];
    gemm_body(A, B, bias, Cin, C, Nn, K, blockIdx.y*64, blockIdx.x*64, As, Bs, Cs, EPI);
}

// Q/K/V in one launch (grid.z selects which projection) — 384 blocks fills the chip
__global__ void __launch_bounds__(128)
qkv_k(const float* __restrict__ A,
      const float* __restrict__ Wq, const float* __restrict__ Wk,
      const float* __restrict__ Wv,
      float* __restrict__ q, float* __restrict__ k, float* __restrict__ v) {
    __shared__ float As[64][16];
    __shared__ float Bs[16][64];
    __shared__ float Cs[64][64];
    int z = blockIdx.z;
    const float* B = (z == 0) ? Wq : (z == 1) ? Wk : Wv;
    float*       C = (z == 0) ? q  : (z == 1) ? k  : v;
    gemm_body(A, B, nullptr, nullptr, C, DD, DD,
              blockIdx.y*64, blockIdx.x*64, As, Bs, Cs, 0);
}

// ---------------- fused causal attention: scores + softmax + AV in one block ----------
// grid: (L/32 i-tiles, B*H); 256 threads; all scores for the 32-row tile kept in SMEM.
__global__ void __launch_bounds__(256) attn_k() {
    int bh = blockIdx.y;
    int b  = bh >> 3, h = bh & 7;
    int it = blockIdx.x;
    int i0 = it * 32;
    int tid = threadIdx.x;

    __shared__ float Qs[32][33];
    __shared__ float KVs[32][33];
    __shared__ float S[32][257];

    // load Q tile
    #pragma unroll
    for (int t = 0; t < 4; t++) {
        int idx = tid + t*256;
        int r = idx >> 5, d = idx & 31;
        Qs[r][d] = g_q[(size_t)(b*LL + i0 + r)*DD + h*32 + d];
    }

    // ---- pass 1: scores for all causal j-tiles ----
    for (int jt = 0; jt <= it; jt++) {
        #pragma unroll
        for (int t = 0; t < 4; t++) {
            int idx = tid + t*256;
            int r = idx >> 5, d = idx & 31;
            KVs[r][d] = g_k[(size_t)(b*LL + jt*32 + r)*DD + h*32 + d];
        }
        __syncthreads();
        #pragma unroll
        for (int t = 0; t < 4; t++) {
            int idx = tid + t*256;
            int il = idx >> 5, jl = idx & 31;
            float s = 0.f;
            #pragma unroll
            for (int d = 0; d < 32; d++) s = fmaf(Qs[il][d], KVs[jl][d], s);
            s *= 0.17677669529663688f;       // 1/sqrt(32)
            if (jt == it && jl > il) s = -1e30f;
            S[il][jt*32 + jl] = s;
        }
        __syncthreads();
    }

    // ---- pass 2: row softmax over [0, ncols) ----
    {
        int w = tid >> 5, lane = tid & 31;
        int ncols = (it + 1) * 32;
        #pragma unroll
        for (int rr = 0; rr < 4; rr++) {
            int r = w*4 + rr;
            float m = -1e30f;
            for (int c = lane; c < ncols; c += 32) m = fmaxf(m, S[r][c]);
            #pragma unroll
            for (int o = 16; o > 0; o >>= 1) m = fmaxf(m, __shfl_xor_sync(0xffffffffu, m, o));
            float sum = 0.f;
            for (int c = lane; c < ncols; c += 32) {
                float e = __expf(S[r][c] - m);
                S[r][c] = e;
                sum += e;
            }
            #pragma unroll
            for (int o = 16; o > 0; o >>= 1) sum += __shfl_xor_sync(0xffffffffu, sum, o);
            float inv = 1.0f / sum;
            for (int c = lane; c < ncols; c += 32) S[r][c] *= inv;
        }
    }
    __syncthreads();

    // ---- pass 3: Z = P @ V ----
    int d  = tid & 31, ib = tid >> 5;
    float acc[4] = {0.f, 0.f, 0.f, 0.f};
    for (int jt = 0; jt <= it; jt++) {
        #pragma unroll
        for (int t = 0; t < 4; t++) {
            int idx = tid + t*256;
            int r = idx >> 5, c = idx & 31;
            KVs[r][c] = g_v[(size_t)(b*LL + jt*32 + r)*DD + h*32 + c];
        }
        __syncthreads();
        #pragma unroll
        for (int jl = 0; jl < 32; jl++) {
            float vv = KVs[jl][d];
            acc[0] = fmaf(S[ib     ][jt*32 + jl], vv, acc[0]);
            acc[1] = fmaf(S[ib +  8][jt*32 + jl], vv, acc[1]);
            acc[2] = fmaf(S[ib + 16][jt*32 + jl], vv, acc[2]);
            acc[3] = fmaf(S[ib + 24][jt*32 + jl], vv, acc[3]);
        }
        __syncthreads();
    }
    #pragma unroll
    for (int t = 0; t < 4; t++)
        g_z[(size_t)(b*LL + i0 + ib + t*8)*DD + h*32 + d] = acc[t];
}

// ---------------- log-softmax over V=2048 (in-place on d_out) ----------------
__global__ void __launch_bounds__(256) lsm_k(float* __restrict__ out) {
    int row = blockIdx.x;
    float* p = out + (size_t)row * VV;
    int tid = threadIdx.x;
    int lid = tid & 31, wid = tid >> 5;
    __shared__ float sh[8];

    float v[8];
    float m = -1e30f;
    #pragma unroll
    for (int i = 0; i < 8; i++) { v[i] = p[tid + i*256]; m = fmaxf(m, v[i]); }
    #pragma unroll
    for (int o = 16; o > 0; o >>= 1) m = fmaxf(m, __shfl_xor_sync(0xffffffffu, m, o));
    if (lid == 0) sh[wid] = m;
    __syncthreads();
    float M = sh[0];
    #pragma unroll
    for (int i = 1; i < 8; i++) M = fmaxf(M, sh[i]);

    float s = 0.f;
    #pragma unroll
    for (int i = 0; i < 8; i++) s += __expf(v[i] - M);
    __syncthreads();
    #pragma unroll
    for (int o = 16; o > 0; o >>= 1) s += __shfl_xor_sync(0xffffffffu, s, o);
    if (lid == 0) sh[wid] = s;
    __syncthreads();
    float S = 0.f;
    #pragma unroll
    for (int i = 0; i < 8; i++) S += sh[i];

    float lse = M + logf(S);
    #pragma unroll
    for (int i = 0; i < 8; i++) p[tid + i*256] = v[i] - lse;
}

// ---------------- host ----------------
extern "C" void kernel_launch(void* const* d_in, const int* in_sizes, int n_in,
                              void* d_out, int out_size) {
    const int*   tok   = (const int*)  d_in[0];
    const int*   pos   = (const int*)  d_in[1];
    // d_in[2]=src, d_in[3]=dst : causal edge lists == dense causal mask; unused.
    const float* vtab  = (const float*)d_in[4];
    const float* ctab  = (const float*)d_in[5];
    const float* ptab  = (const float*)d_in[6];
    const float* ln1_g = (const float*)d_in[7];
    const float* ln1_b = (const float*)d_in[8];
    const float* Wq    = (const float*)d_in[9];
    const float* Wk    = (const float*)d_in[10];
    const float* Wv    = (const float*)d_in[11];
    const float* Wo    = (const float*)d_in[12];
    const float* ln2_g = (const float*)d_in[13];
    const float* ln2_b = (const float*)d_in[14];
    const float* W1    = (const float*)d_in[15];
    const float* b1    = (const float*)d_in[16];
    const float* W2    = (const float*)d_in[17];
    const float* b2    = (const float*)d_in[18];
    const float* lnf_g = (const float*)d_in[19];
    const float* lnf_b = (const float*)d_in[20];
    const float* Wgen  = (const float*)d_in[21];
    const float* bgen  = (const float*)d_in[22];

    float *px, *pxn, *pq, *pk, *pv, *pz, *pff;
    cudaGetSymbolAddress((void**)&px,  g_x);
    cudaGetSymbolAddress((void**)&pxn, g_xn);
    cudaGetSymbolAddress((void**)&pq,  g_q);
    cudaGetSymbolAddress((void**)&pk,  g_k);
    cudaGetSymbolAddress((void**)&pv,  g_v);
    cudaGetSymbolAddress((void**)&pz,  g_z);
    cudaGetSymbolAddress((void**)&pff, g_ff);

    embed_k<<<NTOK, 256>>>(tok, pos, vtab, ctab, ptab);

    dim3 gD  (DD / 64,  NTOK / 64);      // 4 x 32
    dim3 gQKV(DD / 64,  NTOK / 64, 3);   // 4 x 32 x 3
    dim3 gFF (FFD / 64, NTOK / 64);      // 16 x 32
    dim3 gV  (VV / 64,  NTOK / 64);      // 32 x 32

    for (int i = 0; i < NLAY; i++) {
        ln_k<<<NTOK, 256>>>(px, pxn, ln1_g + i*DD, ln1_b + i*DD);
        qkv_k<<<gQKV, 128>>>(pxn, Wq + (size_t)i*DD*DD, Wk + (size_t)i*DD*DD,
                             Wv + (size_t)i*DD*DD, pq, pk, pv);

        attn_k<<<dim3(LL/32, BB*HH), 256>>>();

        gemm_k<<<gD, 128>>>(pz, Wo + (size_t)i*DD*DD, nullptr, px, px, DD, DD, 3);

        ln_k<<<NTOK, 256>>>(px, pxn, ln2_g + i*DD, ln2_b + i*DD);
        gemm_k<<<gFF, 128>>>(pxn, W1 + (size_t)i*DD*FFD, b1 + (size_t)i*FFD,
                             nullptr, pff, FFD, DD, 2);
        gemm_k<<<gD, 128>>>(pff, W2 + (size_t)i*FFD*DD, b2 + (size_t)i*DD,
                            px, px, DD, FFD, 4);
    }

    ln_k<<<NTOK, 256>>>(px, pxn, lnf_g, lnf_b);
    gemm_k<<<gV, 128>>>(pxn, Wgen, bgen, nullptr, (float*)d_out, VV, DD, 1);
    lsm_k<<<NTOK, 256>>>((float*)d_out);
}

// round 9
// speedup vs baseline: 1.3146x; 1.3146x over previous
#include <cuda_runtime.h>
#include <cuda_bf16.h>
#include <mma.h>
#include <math.h>

using namespace nvcuda;

// Problem constants
#define NTOK 2048   // B*L
#define DD   256
#define HH   8
#define DKK  32
#define NLAY 4
#define VV   2048
#define FFD  1024
#define LL   256
#define BB   8
#define EPSF 1e-5f

// ---------------- scratch (no allocation allowed) ----------------
__device__ float g_x [NTOK*DD];
__device__ float g_xn[NTOK*DD];
__device__ float g_q [NTOK*DD];
__device__ float g_k [NTOK*DD];
__device__ float g_v [NTOK*DD];
__device__ float g_z [NTOK*DD];
__device__ float g_ff[NTOK*FFD];

// ---------------- embedding ----------------
__global__ void embed_k(const int* __restrict__ tok, const int* __restrict__ pos,
                        const float* __restrict__ vt, const float* __restrict__ ct,
                        const float* __restrict__ pt) {
    int n = blockIdx.x, d = threadIdx.x;
    int t = tok[n], p = pos[n];
    g_x[n*DD + d] = vt[t*DD + d] * 16.0f          // sqrt(256)
                  + ct[(p % 3)*DD + d]
                  + pt[(p / 3)*DD + d];
}

// ---------------- layernorm (one block per row, D=256) ----------------
__global__ void ln_k(const float* __restrict__ in, float* __restrict__ out,
                     const float* __restrict__ g, const float* __restrict__ b) {
    int n = blockIdx.x, d = threadIdx.x;
    float v = in[n*DD + d];
    __shared__ float sh[16];
    float s = v, s2 = v*v;
    #pragma unroll
    for (int o = 16; o > 0; o >>= 1) {
        s  += __shfl_xor_sync(0xffffffffu, s,  o);
        s2 += __shfl_xor_sync(0xffffffffu, s2, o);
    }
    int wid = d >> 5, lid = d & 31;
    if (lid == 0) { sh[wid] = s; sh[wid + 8] = s2; }
    __syncthreads();
    float ts = 0.f, ts2 = 0.f;
    #pragma unroll
    for (int i = 0; i < 8; i++) { ts += sh[i]; ts2 += sh[i + 8]; }
    float mean = ts * (1.0f/DD);
    float var  = ts2 * (1.0f/DD) - mean*mean;
    out[n*DD + d] = (v - mean) * rsqrtf(var + EPSF) * g[d] + b[d];
}

// ---------------- bf16 WMMA GEMM: C = A(MxK) @ B(KxN) -------------------------
// 64x64 block tile, BK=32, 128 threads = 4 warps (2x2 grid of 32x32 warp tiles),
// m16n16k16 bf16 mma, fp32 accumulate. fp32->bf16 conversion done ONCE at STS.
// EPI: 0=none, 1=bias, 2=bias+relu, 3=residual, 4=bias+residual
template<int EPI>
__device__ __forceinline__ void gemm_body(
        const float* __restrict__ A, const float* __restrict__ B,
        const float* __restrict__ bias, const float* __restrict__ Cin,
        float* __restrict__ C, int Nn, int K,
        int row0, int col0,
        __nv_bfloat16 (*As)[40], __nv_bfloat16 (*Bs)[72], float (*Cs)[68]) {
    int tid = threadIdx.x;
    int w  = tid >> 5;
    int wr = w >> 1, wc = w & 1;               // 2x2 warp grid
    int am = tid >> 1,  aq = (tid & 1) * 16;   // A: row am, 16 k-elems
    int bk = tid >> 2,  bq = (tid & 3) * 16;   // B: k-row bk, 16 n-elems

    wmma::fragment<wmma::matrix_a, 16, 16, 16, __nv_bfloat16, wmma::row_major> af;
    wmma::fragment<wmma::matrix_b, 16, 16, 16, __nv_bfloat16, wmma::row_major> bf;
    wmma::fragment<wmma::accumulator, 16, 16, 16, float> cf[2][2];
    #pragma unroll
    for (int i = 0; i < 2; i++)
        #pragma unroll
        for (int j = 0; j < 2; j++) wmma::fill_fragment(cf[i][j], 0.0f);

    const float* Ap = A + (size_t)(row0 + am)*K + aq;
    const float* Bp = B + (size_t)bk*Nn + col0 + bq;

    float4 a4[4], b4[4];
    #pragma unroll
    for (int u = 0; u < 4; u++) {
        a4[u] = *(const float4*)(Ap + u*4);
        b4[u] = *(const float4*)(Bp + u*4);
    }

    for (int k0 = 0; k0 < K; k0 += 32) {
        #pragma unroll
        for (int u = 0; u < 4; u++) {
            __nv_bfloat162* da = (__nv_bfloat162*)&As[am][aq + u*4];
            da[0] = __floats2bfloat162_rn(a4[u].x, a4[u].y);
            da[1] = __floats2bfloat162_rn(a4[u].z, a4[u].w);
            __nv_bfloat162* db = (__nv_bfloat162*)&Bs[bk][bq + u*4];
            db[0] = __floats2bfloat162_rn(b4[u].x, b4[u].y);
            db[1] = __floats2bfloat162_rn(b4[u].z, b4[u].w);
        }
        __syncthreads();

        if (k0 + 32 < K) {                      // prefetch next k-tile into regs
            #pragma unroll
            for (int u = 0; u < 4; u++) {
                a4[u] = *(const float4*)(Ap + k0 + 32 + u*4);
                b4[u] = *(const float4*)(Bp + (size_t)(k0 + 32)*Nn + u*4);
            }
        }

        #pragma unroll
        for (int kc = 0; kc < 32; kc += 16) {
            #pragma unroll
            for (int mi = 0; mi < 2; mi++) {
                wmma::load_matrix_sync(af, &As[wr*32 + mi*16][kc], 40);
                #pragma unroll
                for (int ni = 0; ni < 2; ni++) {
                    wmma::load_matrix_sync(bf, &Bs[kc][wc*32 + ni*16], 72);
                    wmma::mma_sync(cf[mi][ni], af, bf, cf[mi][ni]);
                }
            }
        }
        __syncthreads();
    }

    #pragma unroll
    for (int mi = 0; mi < 2; mi++)
        #pragma unroll
        for (int ni = 0; ni < 2; ni++)
            wmma::store_matrix_sync(&Cs[wr*32 + mi*16][wc*32 + ni*16],
                                    cf[mi][ni], 68, wmma::mem_row_major);
    __syncthreads();

    for (int idx = tid; idx < 64*64; idx += 128) {
        int r = idx >> 6, c = idx & 63;
        float val = Cs[r][c];
        int gr = row0 + r, gc = col0 + c;
        if (EPI == 1 || EPI == 2 || EPI == 4) val += bias[gc];
        if (EPI == 2)                         val = fmaxf(val, 0.f);
        if (EPI == 3 || EPI == 4)             val += Cin[(size_t)gr*Nn + gc];
        C[(size_t)gr*Nn + gc] = val;
    }
}

template<int EPI>
__global__ void __launch_bounds__(128)
gemm_k(const float* __restrict__ A, const float* __restrict__ B,
       const float* __restrict__ bias, const float* __restrict__ Cin,
       float* __restrict__ C, int Nn, int K) {
    __shared__ __nv_bfloat16 As[64][40];
    __shared__ __nv_bfloat16 Bs[32][72];
    __shared__ float Cs[64][68];
    gemm_body<EPI>(A, B, bias, Cin, C, Nn, K, blockIdx.y*64, blockIdx.x*64, As, Bs, Cs);
}

// Q/K/V in one launch (grid.z selects which projection)
__global__ void __launch_bounds__(128)
qkv_k(const float* __restrict__ A,
      const float* __restrict__ Wq, const float* __restrict__ Wk,
      const float* __restrict__ Wv,
      float* __restrict__ q, float* __restrict__ k, float* __restrict__ v) {
    __shared__ __nv_bfloat16 As[64][40];
    __shared__ __nv_bfloat16 Bs[32][72];
    __shared__ float Cs[64][68];
    int z = blockIdx.z;
    const float* B = (z == 0) ? Wq : (z == 1) ? Wk : Wv;
    float*       C = (z == 0) ? q  : (z == 1) ? k  : v;
    gemm_body<0>(A, B, nullptr, nullptr, C, DD, DD,
                 blockIdx.y*64, blockIdx.x*64, As, Bs, Cs);
}

// ---------------- fused causal attention (LDS-optimized) ------------------------
// grid (L/32, B*H), 256 threads. Q row held in regs (pre-scaled); K staged
// transposed for LDS.128 reads; V staged row-major for LDS.128; P broadcast.
__global__ void __launch_bounds__(256) attn_k() {
    int bh = blockIdx.y;
    int b  = bh >> 3, h = bh & 7;
    int it = blockIdx.x;
    int i0 = it * 32;
    int tid = threadIdx.x;

    __shared__ float Qs[32][33];
    __shared__ float KT[32][36];    // KT[d][j]  (padded 36 for aligned float4)
    __shared__ float Vs[32][36];    // Vs[j][d]
    __shared__ float S [32][260];   // scores / probabilities

    // load Q tile
    #pragma unroll
    for (int t = 0; t < 4; t++) {
        int idx = tid + t*256;
        int r = idx >> 5, d = idx & 31;
        Qs[r][d] = g_q[(size_t)(b*LL + i0 + r)*DD + h*32 + d];
    }
    __syncthreads();

    int il = tid >> 3;              // this thread's query row (8 threads per row)
    int jg = (tid & 7) * 4;         // 4-key group
    float q[32];
    #pragma unroll
    for (int d = 0; d < 32; d++)
        q[d] = Qs[il][d] * 0.17677669529663688f;   // fold 1/sqrt(32) into q

    // ---- pass 1: scores ----
    for (int jt = 0; jt <= it; jt++) {
        #pragma unroll
        for (int t = 0; t < 4; t++) {
            int idx = tid + t*256;
            int r = idx >> 5, d = idx & 31;
            KT[d][r] = g_k[(size_t)(b*LL + jt*32 + r)*DD + h*32 + d];
        }
        __syncthreads();
        float s0 = 0.f, s1 = 0.f, s2 = 0.f, s3 = 0.f;
        #pragma unroll
        for (int d = 0; d < 32; d++) {
            float4 kv = *(const float4*)&KT[d][jg];
            s0 = fmaf(q[d], kv.x, s0);
            s1 = fmaf(q[d], kv.y, s1);
            s2 = fmaf(q[d], kv.z, s2);
            s3 = fmaf(q[d], kv.w, s3);
        }
        if (jt == it) {                           // causal mask inside diagonal tile
            if (jg + 0 > il) s0 = -1e30f;
            if (jg + 1 > il) s1 = -1e30f;
            if (jg + 2 > il) s2 = -1e30f;
            if (jg + 3 > il) s3 = -1e30f;
        }
        *(float4*)&S[il][jt*32 + jg] = make_float4(s0, s1, s2, s3);
        __syncthreads();
    }

    // ---- pass 2: row softmax over [0, ncols) ----
    {
        int w = tid >> 5, lane = tid & 31;
        int ncols = (it + 1) * 32;
        #pragma unroll
        for (int rr = 0; rr < 4; rr++) {
            int r = w*4 + rr;
            float m = -1e30f;
            for (int c = lane; c < ncols; c += 32) m = fmaxf(m, S[r][c]);
            #pragma unroll
            for (int o = 16; o > 0; o >>= 1) m = fmaxf(m, __shfl_xor_sync(0xffffffffu, m, o));
            float sum = 0.f;
            for (int c = lane; c < ncols; c += 32) {
                float e = __expf(S[r][c] - m);
                S[r][c] = e;
                sum += e;
            }
            #pragma unroll
            for (int o = 16; o > 0; o >>= 1) sum += __shfl_xor_sync(0xffffffffu, sum, o);
            float inv = 1.0f / sum;
            for (int c = lane; c < ncols; c += 32) S[r][c] *= inv;
        }
    }
    __syncthreads();

    // ---- pass 3: Z = P @ V ----
    int dg = (tid & 7) * 4;         // 4 head-dims per thread; same il as pass 1
    float z0 = 0.f, z1 = 0.f, z2 = 0.f, z3 = 0.f;
    for (int jt = 0; jt <= it; jt++) {
        #pragma unroll
        for (int t = 0; t < 4; t++) {
            int idx = tid + t*256;
            int r = idx >> 5, d = idx & 31;
            Vs[r][d] = g_v[(size_t)(b*LL + jt*32 + r)*DD + h*32 + d];
        }
        __syncthreads();
        #pragma unroll
        for (int j = 0; j < 32; j++) {
            float pj = S[il][jt*32 + j];          // broadcast among 8 threads
            float4 vv = *(const float4*)&Vs[j][dg];
            z0 = fmaf(pj, vv.x, z0);
            z1 = fmaf(pj, vv.y, z1);
            z2 = fmaf(pj, vv.z, z2);
            z3 = fmaf(pj, vv.w, z3);
        }
        __syncthreads();
    }
    *(float4*)&g_z[(size_t)(b*LL + i0 + il)*DD + h*32 + dg] = make_float4(z0, z1, z2, z3);
}

// ---------------- log-softmax over V=2048 (in-place on d_out) ----------------
__global__ void __launch_bounds__(256) lsm_k(float* __restrict__ out) {
    int row = blockIdx.x;
    float* p = out + (size_t)row * VV;
    int tid = threadIdx.x;
    int lid = tid & 31, wid = tid >> 5;
    __shared__ float sh[8];

    float v[8];
    float m = -1e30f;
    #pragma unroll
    for (int i = 0; i < 8; i++) { v[i] = p[tid + i*256]; m = fmaxf(m, v[i]); }
    #pragma unroll
    for (int o = 16; o > 0; o >>= 1) m = fmaxf(m, __shfl_xor_sync(0xffffffffu, m, o));
    if (lid == 0) sh[wid] = m;
    __syncthreads();
    float M = sh[0];
    #pragma unroll
    for (int i = 1; i < 8; i++) M = fmaxf(M, sh[i]);

    float s = 0.f;
    #pragma unroll
    for (int i = 0; i < 8; i++) s += __expf(v[i] - M);
    __syncthreads();
    #pragma unroll
    for (int o = 16; o > 0; o >>= 1) s += __shfl_xor_sync(0xffffffffu, s, o);
    if (lid == 0) sh[wid] = s;
    __syncthreads();
    float S = 0.f;
    #pragma unroll
    for (int i = 0; i < 8; i++) S += sh[i];

    float lse = M + logf(S);
    #pragma unroll
    for (int i = 0; i < 8; i++) p[tid + i*256] = v[i] - lse;
}

// ---------------- host ----------------
extern "C" void kernel_launch(void* const* d_in, const int* in_sizes, int n_in,
                              void* d_out, int out_size) {
    const int*   tok   = (const int*)  d_in[0];
    const int*   pos   = (const int*)  d_in[1];
    // d_in[2]=src, d_in[3]=dst : causal edge lists == dense causal mask; unused.
    const float* vtab  = (const float*)d_in[4];
    const float* ctab  = (const float*)d_in[5];
    const float* ptab  = (const float*)d_in[6];
    const float* ln1_g = (const float*)d_in[7];
    const float* ln1_b = (const float*)d_in[8];
    const float* Wq    = (const float*)d_in[9];
    const float* Wk    = (const float*)d_in[10];
    const float* Wv    = (const float*)d_in[11];
    const float* Wo    = (const float*)d_in[12];
    const float* ln2_g = (const float*)d_in[13];
    const float* ln2_b = (const float*)d_in[14];
    const float* W1    = (const float*)d_in[15];
    const float* b1    = (const float*)d_in[16];
    const float* W2    = (const float*)d_in[17];
    const float* b2    = (const float*)d_in[18];
    const float* lnf_g = (const float*)d_in[19];
    const float* lnf_b = (const float*)d_in[20];
    const float* Wgen  = (const float*)d_in[21];
    const float* bgen  = (const float*)d_in[22];

    float *px, *pxn, *pq, *pk, *pv, *pz, *pff;
    cudaGetSymbolAddress((void**)&px,  g_x);
    cudaGetSymbolAddress((void**)&pxn, g_xn);
    cudaGetSymbolAddress((void**)&pq,  g_q);
    cudaGetSymbolAddress((void**)&pk,  g_k);
    cudaGetSymbolAddress((void**)&pv,  g_v);
    cudaGetSymbolAddress((void**)&pz,  g_z);
    cudaGetSymbolAddress((void**)&pff, g_ff);

    embed_k<<<NTOK, 256>>>(tok, pos, vtab, ctab, ptab);

    dim3 gD  (DD / 64,  NTOK / 64);      // 4 x 32
    dim3 gQKV(DD / 64,  NTOK / 64, 3);   // 4 x 32 x 3
    dim3 gFF (FFD / 64, NTOK / 64);      // 16 x 32
    dim3 gV  (VV / 64,  NTOK / 64);      // 32 x 32

    for (int i = 0; i < NLAY; i++) {
        ln_k<<<NTOK, 256>>>(px, pxn, ln1_g + i*DD, ln1_b + i*DD);
        qkv_k<<<gQKV, 128>>>(pxn, Wq + (size_t)i*DD*DD, Wk + (size_t)i*DD*DD,
                             Wv + (size_t)i*DD*DD, pq, pk, pv);

        attn_k<<<dim3(LL/32, BB*HH), 256>>>();

        gemm_k<3><<<gD, 128>>>(pz, Wo + (size_t)i*DD*DD, nullptr, px, px, DD, DD);

        ln_k<<<NTOK, 256>>>(px, pxn, ln2_g + i*DD, ln2_b + i*DD);
        gemm_k<2><<<gFF, 128>>>(pxn, W1 + (size_t)i*DD*FFD, b1 + (size_t)i*FFD,
                                nullptr, pff, FFD, DD);
        gemm_k<4><<<gD, 128>>>(pff, W2 + (size_t)i*FFD*DD, b2 + (size_t)i*DD,
                               px, px, DD, FFD);
    }

    ln_k<<<NTOK, 256>>>(px, pxn, lnf_g, lnf_b);
    gemm_k<1><<<gV, 128>>>(pxn, Wgen, bgen, nullptr, (float*)d_out, VV, DD);
    lsm_k<<<NTOK, 256>>>((float*)d_out);
}

// round 11
// speedup vs baseline: 1.8000x; 1.3692x over previous
#include <cuda_runtime.h>
#include <cuda_bf16.h>
#include <mma.h>
#include <math.h>
#include <stdint.h>

using namespace nvcuda;

// Problem constants
#define NTOK 2048   // B*L
#define DD   256
#define HH   8
#define DKK  32
#define NLAY 4
#define VV   2048
#define FFD  1024
#define LL   256
#define BB   8
#define EPSF 1e-5f

// ---------------- scratch (no allocation allowed) ----------------
__device__ float g_x [NTOK*DD];
__device__ float g_xn[NTOK*DD];
__device__ float g_q [NTOK*DD];
__device__ float g_k [NTOK*DD];
__device__ float g_v [NTOK*DD];
__device__ float g_z [NTOK*DD];
__device__ float g_ff[NTOK*FFD];

// ---------------- embedding ----------------
__global__ void embed_k(const int* __restrict__ tok, const int* __restrict__ pos,
                        const float* __restrict__ vt, const float* __restrict__ ct,
                        const float* __restrict__ pt) {
    int n = blockIdx.x, d = threadIdx.x;
    int t = tok[n], p = pos[n];
    g_x[n*DD + d] = vt[t*DD + d] * 16.0f          // sqrt(256)
                  + ct[(p % 3)*DD + d]
                  + pt[(p / 3)*DD + d];
}

// ---------------- layernorm (one block per row, D=256) ----------------
__global__ void ln_k(const float* __restrict__ in, float* __restrict__ out,
                     const float* __restrict__ g, const float* __restrict__ b) {
    int n = blockIdx.x, d = threadIdx.x;
    float v = in[n*DD + d];
    __shared__ float sh[16];
    float s = v, s2 = v*v;
    #pragma unroll
    for (int o = 16; o > 0; o >>= 1) {
        s  += __shfl_xor_sync(0xffffffffu, s,  o);
        s2 += __shfl_xor_sync(0xffffffffu, s2, o);
    }
    int wid = d >> 5, lid = d & 31;
    if (lid == 0) { sh[wid] = s; sh[wid + 8] = s2; }
    __syncthreads();
    float ts = 0.f, ts2 = 0.f;
    #pragma unroll
    for (int i = 0; i < 8; i++) { ts += sh[i]; ts2 += sh[i + 8]; }
    float mean = ts * (1.0f/DD);
    float var  = ts2 * (1.0f/DD) - mean*mean;
    out[n*DD + d] = (v - mean) * rsqrtf(var + EPSF) * g[d] + b[d];
}

// ---------------- bf16 WMMA GEMM: C = A(MxK) @ B(KxN) -------------------------
// (unchanged from the 553us passing kernel)
template<int EPI>
__device__ __forceinline__ void gemm_body(
        const float* __restrict__ A, const float* __restrict__ B,
        const float* __restrict__ bias, const float* __restrict__ Cin,
        float* __restrict__ C, int Nn, int K,
        int row0, int col0,
        __nv_bfloat16 (*As)[40], __nv_bfloat16 (*Bs)[72], float (*Cs)[68]) {
    int tid = threadIdx.x;
    int w  = tid >> 5;
    int wr = w >> 1, wc = w & 1;               // 2x2 warp grid
    int am = tid >> 1,  aq = (tid & 1) * 16;   // A: row am, 16 k-elems
    int bk = tid >> 2,  bq = (tid & 3) * 16;   // B: k-row bk, 16 n-elems

    wmma::fragment<wmma::matrix_a, 16, 16, 16, __nv_bfloat16, wmma::row_major> af;
    wmma::fragment<wmma::matrix_b, 16, 16, 16, __nv_bfloat16, wmma::row_major> bf;
    wmma::fragment<wmma::accumulator, 16, 16, 16, float> cf[2][2];
    #pragma unroll
    for (int i = 0; i < 2; i++)
        #pragma unroll
        for (int j = 0; j < 2; j++) wmma::fill_fragment(cf[i][j], 0.0f);

    const float* Ap = A + (size_t)(row0 + am)*K + aq;
    const float* Bp = B + (size_t)bk*Nn + col0 + bq;

    float4 a4[4], b4[4];
    #pragma unroll
    for (int u = 0; u < 4; u++) {
        a4[u] = *(const float4*)(Ap + u*4);
        b4[u] = *(const float4*)(Bp + u*4);
    }

    for (int k0 = 0; k0 < K; k0 += 32) {
        #pragma unroll
        for (int u = 0; u < 4; u++) {
            __nv_bfloat162* da = (__nv_bfloat162*)&As[am][aq + u*4];
            da[0] = __floats2bfloat162_rn(a4[u].x, a4[u].y);
            da[1] = __floats2bfloat162_rn(a4[u].z, a4[u].w);
            __nv_bfloat162* db = (__nv_bfloat162*)&Bs[bk][bq + u*4];
            db[0] = __floats2bfloat162_rn(b4[u].x, b4[u].y);
            db[1] = __floats2bfloat162_rn(b4[u].z, b4[u].w);
        }
        __syncthreads();

        if (k0 + 32 < K) {                      // prefetch next k-tile into regs
            #pragma unroll
            for (int u = 0; u < 4; u++) {
                a4[u] = *(const float4*)(Ap + k0 + 32 + u*4);
                b4[u] = *(const float4*)(Bp + (size_t)(k0 + 32)*Nn + u*4);
            }
        }

        #pragma unroll
        for (int kc = 0; kc < 32; kc += 16) {
            #pragma unroll
            for (int mi = 0; mi < 2; mi++) {
                wmma::load_matrix_sync(af, &As[wr*32 + mi*16][kc], 40);
                #pragma unroll
                for (int ni = 0; ni < 2; ni++) {
                    wmma::load_matrix_sync(bf, &Bs[kc][wc*32 + ni*16], 72);
                    wmma::mma_sync(cf[mi][ni], af, bf, cf[mi][ni]);
                }
            }
        }
        __syncthreads();
    }

    #pragma unroll
    for (int mi = 0; mi < 2; mi++)
        #pragma unroll
        for (int ni = 0; ni < 2; ni++)
            wmma::store_matrix_sync(&Cs[wr*32 + mi*16][wc*32 + ni*16],
                                    cf[mi][ni], 68, wmma::mem_row_major);
    __syncthreads();

    for (int idx = tid; idx < 64*64; idx += 128) {
        int r = idx >> 6, c = idx & 63;
        float val = Cs[r][c];
        int gr = row0 + r, gc = col0 + c;
        if (EPI == 1 || EPI == 2 || EPI == 4) val += bias[gc];
        if (EPI == 2)                         val = fmaxf(val, 0.f);
        if (EPI == 3 || EPI == 4)             val += Cin[(size_t)gr*Nn + gc];
        C[(size_t)gr*Nn + gc] = val;
    }
}

template<int EPI>
__global__ void __launch_bounds__(128)
gemm_k(const float* __restrict__ A, const float* __restrict__ B,
       const float* __restrict__ bias, const float* __restrict__ Cin,
       float* __restrict__ C, int Nn, int K) {
    __shared__ __nv_bfloat16 As[64][40];
    __shared__ __nv_bfloat16 Bs[32][72];
    __shared__ float Cs[64][68];
    gemm_body<EPI>(A, B, bias, Cin, C, Nn, K, blockIdx.y*64, blockIdx.x*64, As, Bs, Cs);
}

// Q/K/V in one launch (grid.z selects which projection)
__global__ void __launch_bounds__(128)
qkv_k(const float* __restrict__ A,
      const float* __restrict__ Wq, const float* __restrict__ Wk,
      const float* __restrict__ Wv,
      float* __restrict__ q, float* __restrict__ k, float* __restrict__ v) {
    __shared__ __nv_bfloat16 As[64][40];
    __shared__ __nv_bfloat16 Bs[32][72];
    __shared__ float Cs[64][68];
    int z = blockIdx.z;
    const float* B = (z == 0) ? Wq : (z == 1) ? Wk : Wv;
    float*       C = (z == 0) ? q  : (z == 1) ? k  : v;
    gemm_body<0>(A, B, nullptr, nullptr, C, DD, DD,
                 blockIdx.y*64, blockIdx.x*64, As, Bs, Cs);
}

// ---------------- flash attention, warp-level mma.m16n8k16 bf16 -----------------
// grid (64 bh, 4 i-tiles), 128 threads = 4 warps, each warp owns a 16-row strip.
// K/V/Q staged to smem ONCE (single barrier); mainloop barrier-free per warp.
__device__ __forceinline__ void mma_bf16(float* c, const uint32_t* a,
                                         uint32_t b0, uint32_t b1) {
    asm volatile(
        "mma.sync.aligned.m16n8k16.row.col.f32.bf16.bf16.f32 "
        "{%0,%1,%2,%3}, {%4,%5,%6,%7}, {%8,%9}, {%0,%1,%2,%3};"
        : "+f"(c[0]), "+f"(c[1]), "+f"(c[2]), "+f"(c[3])
        : "r"(a[0]), "r"(a[1]), "r"(a[2]), "r"(a[3]), "r"(b0), "r"(b1));
}

__device__ __forceinline__ uint32_t pk2(float x, float y) {
    __nv_bfloat162 h = __floats2bfloat162_rn(x, y);
    return *(uint32_t*)&h;
}

__global__ void __launch_bounds__(128) attn_k() {
    int bh = blockIdx.x;
    int b  = bh >> 3, h = bh & 7;
    int it = (int)gridDim.y - 1 - (int)blockIdx.y;   // heavy tiles first
    int i0 = it * 64;
    int nkeys = i0 + 64;
    int tid = threadIdx.x, lane = tid & 31, w = tid >> 5;

    __shared__ __nv_bfloat16 Ks[256][40];    // K row-major  [j][d], pad 40 (20 words)
    __shared__ __nv_bfloat16 VT[32][264];    // V transposed [d][j], pad 264 (132 words)
    __shared__ __nv_bfloat16 Qs[64][40];     // Q (pre-scaled) [r][d]

    const float SC = 0.17677669529663688f;   // 1/sqrt(32)

    // ---- stage Q (scaled), K, V^T as bf16 ----
    for (int p = tid; p < 64*16; p += 128) {
        int r = p >> 4, dp = (p & 15) * 2;
        float2 qv = *(const float2*)&g_q[(size_t)(b*LL + i0 + r)*DD + h*32 + dp];
        *(uint32_t*)&Qs[r][dp] = pk2(qv.x * SC, qv.y * SC);
    }
    for (int p = tid; p < nkeys*16; p += 128) {
        int r = p >> 4, dp = (p & 15) * 2;
        float2 kv = *(const float2*)&g_k[(size_t)(b*LL + r)*DD + h*32 + dp];
        *(uint32_t*)&Ks[r][dp] = pk2(kv.x, kv.y);
    }
    for (int p = tid; p < (nkeys >> 1)*32; p += 128) {
        int jj = (p >> 5) * 2, d = p & 31;
        float v0 = g_v[(size_t)(b*LL + jj    )*DD + h*32 + d];
        float v1 = g_v[(size_t)(b*LL + jj + 1)*DD + h*32 + d];
        *(uint32_t*)&VT[d][jj] = pk2(v0, v1);
    }
    __syncthreads();

    // ---- per-warp flash mainloop (no barriers) ----
    int g  = lane >> 2;            // group id (row / n-col within fragment)
    int t2 = (lane & 3) * 2;       // in-group pair offset
    int ib = w * 16;               // warp's row strip within block tile
    int gi = i0 + ib;              // global strip base

    uint32_t qa[2][4];             // Q A-frags for k-chunks 0,1
    #pragma unroll
    for (int kc = 0; kc < 2; kc++) {
        qa[kc][0] = *(uint32_t*)&Qs[ib +     g][kc*16 +     t2];
        qa[kc][1] = *(uint32_t*)&Qs[ib + 8 + g][kc*16 +     t2];
        qa[kc][2] = *(uint32_t*)&Qs[ib +     g][kc*16 + 8 + t2];
        qa[kc][3] = *(uint32_t*)&Qs[ib + 8 + g][kc*16 + 8 + t2];
    }

    float o[4][4];
    #pragma unroll
    for (int dc = 0; dc < 4; dc++)
        #pragma unroll
        for (int u = 0; u < 4; u++) o[dc][u] = 0.f;
    float mA = -1e30f, mB = -1e30f, lA = 0.f, lB = 0.f;

    int ntiles = (gi >> 4) + 1;    // causal: j-tiles 0 .. gi/16
    for (int jt = 0; jt < ntiles; jt++) {
        int j0 = jt << 4;
        float sL[4] = {0.f, 0.f, 0.f, 0.f};
        float sH[4] = {0.f, 0.f, 0.f, 0.f};
        #pragma unroll
        for (int kc = 0; kc < 2; kc++) {
            uint32_t b0 = *(uint32_t*)&Ks[j0 +     g][kc*16 +     t2];
            uint32_t b1 = *(uint32_t*)&Ks[j0 +     g][kc*16 + 8 + t2];
            mma_bf16(sL, qa[kc], b0, b1);
            b0 = *(uint32_t*)&Ks[j0 + 8 + g][kc*16 +     t2];
            b1 = *(uint32_t*)&Ks[j0 + 8 + g][kc*16 + 8 + t2];
            mma_bf16(sH, qa[kc], b0, b1);
        }

        if (jt == ntiles - 1) {                    // diagonal tile: causal mask
            int rA = gi + g, rB = rA + 8;
            int cL = j0 + t2, cH = j0 + 8 + t2;
            if (cL     > rA) sL[0] = -1e30f;
            if (cL + 1 > rA) sL[1] = -1e30f;
            if (cL     > rB) sL[2] = -1e30f;
            if (cL + 1 > rB) sL[3] = -1e30f;
            if (cH     > rA) sH[0] = -1e30f;
            if (cH + 1 > rA) sH[1] = -1e30f;
            if (cH     > rB) sH[2] = -1e30f;
            if (cH + 1 > rB) sH[3] = -1e30f;
        }

        // online softmax update (rows rA=g, rB=g+8; replicated over 4-lane groups)
        float tA = fmaxf(fmaxf(sL[0], sL[1]), fmaxf(sH[0], sH[1]));
        float tB = fmaxf(fmaxf(sL[2], sL[3]), fmaxf(sH[2], sH[3]));
        tA = fmaxf(tA, __shfl_xor_sync(0xffffffffu, tA, 1));
        tA = fmaxf(tA, __shfl_xor_sync(0xffffffffu, tA, 2));
        tB = fmaxf(tB, __shfl_xor_sync(0xffffffffu, tB, 1));
        tB = fmaxf(tB, __shfl_xor_sync(0xffffffffu, tB, 2));
        float mnA = fmaxf(mA, tA), mnB = fmaxf(mB, tB);
        float scA = __expf(mA - mnA), scB = __expf(mB - mnB);
        mA = mnA; mB = mnB;

        float pL0 = __expf(sL[0] - mnA), pL1 = __expf(sL[1] - mnA);
        float pL2 = __expf(sL[2] - mnB), pL3 = __expf(sL[3] - mnB);
        float pH0 = __expf(sH[0] - mnA), pH1 = __expf(sH[1] - mnA);
        float pH2 = __expf(sH[2] - mnB), pH3 = __expf(sH[3] - mnB);

        float rsA = pL0 + pL1 + pH0 + pH1;
        float rsB = pL2 + pL3 + pH2 + pH3;
        rsA += __shfl_xor_sync(0xffffffffu, rsA, 1);
        rsA += __shfl_xor_sync(0xffffffffu, rsA, 2);
        rsB += __shfl_xor_sync(0xffffffffu, rsB, 1);
        rsB += __shfl_xor_sync(0xffffffffu, rsB, 2);
        lA = lA*scA + rsA;
        lB = lB*scB + rsB;

        #pragma unroll
        for (int dc = 0; dc < 4; dc++) {
            o[dc][0] *= scA; o[dc][1] *= scA;
            o[dc][2] *= scB; o[dc][3] *= scB;
        }

        // P (C-layout) == A-layout for m16n8k16 -> direct reinterpretation
        uint32_t pa[4];
        pa[0] = pk2(pL0, pL1);
        pa[1] = pk2(pL2, pL3);
        pa[2] = pk2(pH0, pH1);
        pa[3] = pk2(pH2, pH3);

        #pragma unroll
        for (int dc = 0; dc < 4; dc++) {
            uint32_t b0 = *(uint32_t*)&VT[dc*8 + g][j0 +     t2];
            uint32_t b1 = *(uint32_t*)&VT[dc*8 + g][j0 + 8 + t2];
            mma_bf16(o[dc], pa, b0, b1);
        }
    }

    // ---- normalize + write out ----
    float iA = 1.0f / lA, iB = 1.0f / lB;
    int rA = gi + g, rB = rA + 8;
    #pragma unroll
    for (int dc = 0; dc < 4; dc++) {
        *(float2*)&g_z[(size_t)(b*LL + rA)*DD + h*32 + dc*8 + t2] =
            make_float2(o[dc][0]*iA, o[dc][1]*iA);
        *(float2*)&g_z[(size_t)(b*LL + rB)*DD + h*32 + dc*8 + t2] =
            make_float2(o[dc][2]*iB, o[dc][3]*iB);
    }
}

// ---------------- log-softmax over V=2048 (in-place on d_out) ----------------
__global__ void __launch_bounds__(256) lsm_k(float* __restrict__ out) {
    int row = blockIdx.x;
    float* p = out + (size_t)row * VV;
    int tid = threadIdx.x;
    int lid = tid & 31, wid = tid >> 5;
    __shared__ float sh[8];

    float v[8];
    float m = -1e30f;
    #pragma unroll
    for (int i = 0; i < 8; i++) { v[i] = p[tid + i*256]; m = fmaxf(m, v[i]); }
    #pragma unroll
    for (int o = 16; o > 0; o >>= 1) m = fmaxf(m, __shfl_xor_sync(0xffffffffu, m, o));
    if (lid == 0) sh[wid] = m;
    __syncthreads();
    float M = sh[0];
    #pragma unroll
    for (int i = 1; i < 8; i++) M = fmaxf(M, sh[i]);

    float s = 0.f;
    #pragma unroll
    for (int i = 0; i < 8; i++) s += __expf(v[i] - M);
    __syncthreads();
    #pragma unroll
    for (int o = 16; o > 0; o >>= 1) s += __shfl_xor_sync(0xffffffffu, s, o);
    if (lid == 0) sh[wid] = s;
    __syncthreads();
    float S = 0.f;
    #pragma unroll
    for (int i = 0; i < 8; i++) S += sh[i];

    float lse = M + logf(S);
    #pragma unroll
    for (int i = 0; i < 8; i++) p[tid + i*256] = v[i] - lse;
}

// ---------------- host ----------------
extern "C" void kernel_launch(void* const* d_in, const int* in_sizes, int n_in,
                              void* d_out, int out_size) {
    const int*   tok   = (const int*)  d_in[0];
    const int*   pos   = (const int*)  d_in[1];
    // d_in[2]=src, d_in[3]=dst : causal edge lists == dense causal mask; unused.
    const float* vtab  = (const float*)d_in[4];
    const float* ctab  = (const float*)d_in[5];
    const float* ptab  = (const float*)d_in[6];
    const float* ln1_g = (const float*)d_in[7];
    const float* ln1_b = (const float*)d_in[8];
    const float* Wq    = (const float*)d_in[9];
    const float* Wk    = (const float*)d_in[10];
    const float* Wv    = (const float*)d_in[11];
    const float* Wo    = (const float*)d_in[12];
    const float* ln2_g = (const float*)d_in[13];
    const float* ln2_b = (const float*)d_in[14];
    const float* W1    = (const float*)d_in[15];
    const float* b1    = (const float*)d_in[16];
    const float* W2    = (const float*)d_in[17];
    const float* b2    = (const float*)d_in[18];
    const float* lnf_g = (const float*)d_in[19];
    const float* lnf_b = (const float*)d_in[20];
    const float* Wgen  = (const float*)d_in[21];
    const float* bgen  = (const float*)d_in[22];

    float *px, *pxn, *pq, *pk, *pv, *pz, *pff;
    cudaGetSymbolAddress((void**)&px,  g_x);
    cudaGetSymbolAddress((void**)&pxn, g_xn);
    cudaGetSymbolAddress((void**)&pq,  g_q);
    cudaGetSymbolAddress((void**)&pk,  g_k);
    cudaGetSymbolAddress((void**)&pv,  g_v);
    cudaGetSymbolAddress((void**)&pz,  g_z);
    cudaGetSymbolAddress((void**)&pff, g_ff);

    embed_k<<<NTOK, 256>>>(tok, pos, vtab, ctab, ptab);

    dim3 gD  (DD / 64,  NTOK / 64);      // 4 x 32
    dim3 gQKV(DD / 64,  NTOK / 64, 3);   // 4 x 32 x 3
    dim3 gFF (FFD / 64, NTOK / 64);      // 16 x 32
    dim3 gV  (VV / 64,  NTOK / 64);      // 32 x 32

    for (int i = 0; i < NLAY; i++) {
        ln_k<<<NTOK, 256>>>(px, pxn, ln1_g + i*DD, ln1_b + i*DD);
        qkv_k<<<gQKV, 128>>>(pxn, Wq + (size_t)i*DD*DD, Wk + (size_t)i*DD*DD,
                             Wv + (size_t)i*DD*DD, pq, pk, pv);

        attn_k<<<dim3(BB*HH, LL/64), 128>>>();

        gemm_k<3><<<gD, 128>>>(pz, Wo + (size_t)i*DD*DD, nullptr, px, px, DD, DD);

        ln_k<<<NTOK, 256>>>(px, pxn, ln2_g + i*DD, ln2_b + i*DD);
        gemm_k<2><<<gFF, 128>>>(pxn, W1 + (size_t)i*DD*FFD, b1 + (size_t)i*FFD,
                                nullptr, pff, FFD, DD);
        gemm_k<4><<<gD, 128>>>(pff, W2 + (size_t)i*FFD*DD, b2 + (size_t)i*DD,
                               px, px, DD, FFD);
    }

    ln_k<<<NTOK, 256>>>(px, pxn, lnf_g, lnf_b);
    gemm_k<1><<<gV, 128>>>(pxn, Wgen, bgen, nullptr, (float*)d_out, VV, DD);
    lsm_k<<<NTOK, 256>>>((float*)d_out);
}